// round 1
// baseline (speedup 1.0000x reference)
#include <cuda_runtime.h>
#include <cstddef>

// ---------------- problem constants ----------------
#define B_    2
#define S_    1024
#define DIN_  64
#define D_    512
#define K_    16
#define KU_   3
#define L_    2
#define M_    2
#define H_    2048
#define R_    (B_ * S_)                 // 2048 rows (b*S + t)
#define SPECC (2 * K_ * D_)             // 16384 spectral columns of U
#define UCOLS (SPECC + KU_ * D_)        // 17920 = spectral + AR columns
#define EPS_  1e-5f

// ---------------- scratch (static device globals; no allocation) ----------------
__device__ float g_x[R_ * D_];                       // 4 MB   current residual stream
__device__ float g_z[R_ * D_];                       // 4 MB   layer input copy
__device__ float g_h[R_ * D_];                       // 4 MB   rmsnorm output
__device__ float g_U[(size_t)R_ * UCOLS];            // 147 MB [Up | Um | h, h<<1, h<<2]
__device__ float g_W[(size_t)D_ * UCOLS];            // 37 MB  fused [sig4*mp | sig4*mm | M_u] weights (N,K layout)
__device__ float g_m1[(size_t)R_ * 2 * H_];          // 33 MB  fc1 output
__device__ float g_m2[(size_t)R_ * H_];              // 17 MB  gated

// ---------------- generic NT GEMM: C(M,N) = A(M,K) * B(N,K)^T ----------------
// BM=BN=64, BK=16, 256 threads, 4x4 micro tile. All K multiples of 16, M,N multiples of 64.
__global__ __launch_bounds__(256) void gemm_nt(
    const float* __restrict__ A, const float* __restrict__ B, float* __restrict__ C,
    int M, int N, int K, int accum)
{
    __shared__ float As[16][65];
    __shared__ float Bs[16][65];
    const int bm = blockIdx.y * 64;
    const int bn = blockIdx.x * 64;
    const int tid = threadIdx.x;
    const int tx = tid & 15;        // output column group
    const int ty = tid >> 4;        // output row group
    const int lr = tid >> 2;        // load row within tile (0..63)
    const int lk = (tid & 3) << 2;  // load k offset (0,4,8,12)

    const float* Ap = A + (size_t)(bm + lr) * K + lk;
    const float* Bp = B + (size_t)(bn + lr) * K + lk;

    float acc[4][4] = {};

    for (int k0 = 0; k0 < K; k0 += 16) {
        float4 av = *(const float4*)(Ap + k0);
        float4 bv = *(const float4*)(Bp + k0);
        __syncthreads();
        As[lk + 0][lr] = av.x; As[lk + 1][lr] = av.y;
        As[lk + 2][lr] = av.z; As[lk + 3][lr] = av.w;
        Bs[lk + 0][lr] = bv.x; Bs[lk + 1][lr] = bv.y;
        Bs[lk + 2][lr] = bv.z; Bs[lk + 3][lr] = bv.w;
        __syncthreads();
#pragma unroll
        for (int kk = 0; kk < 16; kk++) {
            float a[4], b[4];
#pragma unroll
            for (int i = 0; i < 4; i++) a[i] = As[kk][ty * 4 + i];
#pragma unroll
            for (int j = 0; j < 4; j++) b[j] = Bs[kk][tx * 4 + j];
#pragma unroll
            for (int i = 0; i < 4; i++)
#pragma unroll
                for (int j = 0; j < 4; j++)
                    acc[i][j] += a[i] * b[j];
        }
    }

#pragma unroll
    for (int i = 0; i < 4; i++) {
        const int r = bm + ty * 4 + i;
#pragma unroll
        for (int j = 0; j < 4; j++) {
            const int c = bn + tx * 4 + j;
            const size_t idx = (size_t)r * N + c;
            C[idx] = accum ? (C[idx] + acc[i][j]) : acc[i][j];
        }
    }
}

// ---------------- causal spectral convolution ----------------
// For block (d-tile, t-tile, b*K+k):
//   Up[t,d] = sum_i phi[t-i,k] * h[b,i,d]
//   Um[t,d] = sgn[t] * sum_i phi[t-i,k] * sgn[i] * h[b,i,d]
// A-operand generated from phi in shared; causal i-tiles only.
__global__ __launch_bounds__(256) void conv_k(
    const float* __restrict__ h, const float* __restrict__ phi, float* __restrict__ U)
{
    __shared__ float Xsh[16][64];   // h tile: [i][d]
    __shared__ float Psh[80];       // phi lags [t0-i0-15 .. t0-i0+63]

    const int d0 = blockIdx.x * 64;
    const int t0 = blockIdx.y * 64;
    const int b  = blockIdx.z / K_;
    const int k  = blockIdx.z % K_;
    const int tid = threadIdx.x;
    const int tx = tid & 15;
    const int ty = tid >> 4;

    float accp[4][4] = {};
    float accm[4][4] = {};

    const int imax = (t0 + 64 < S_) ? (t0 + 64) : S_;

    for (int i0 = 0; i0 < imax; i0 += 16) {
        // stage loads in registers
        const int ii = tid >> 4;          // 0..15
        const int cc = (tid & 15) << 2;   // 0..60
        float4 xv = *(const float4*)&h[((size_t)(b * S_ + i0 + ii)) * D_ + d0 + cc];
        float pv = 0.f;
        if (tid < 79) {
            const int lag = t0 - i0 - 15 + tid;
            if (lag >= 0 && lag < S_) pv = phi[lag * K_ + k];
        }
        __syncthreads();
        *(float4*)&Xsh[ii][cc] = xv;
        if (tid < 79) Psh[tid] = pv;
        __syncthreads();

#pragma unroll
        for (int kk = 0; kk < 16; kk++) {
            const float s = ((i0 + kk) & 1) ? -1.f : 1.f;
            float a[4], bb[4], bs[4];
#pragma unroll
            for (int i = 0; i < 4; i++) a[i] = Psh[ty * 4 + i - kk + 15];
#pragma unroll
            for (int j = 0; j < 4; j++) { bb[j] = Xsh[kk][tx * 4 + j]; bs[j] = s * bb[j]; }
#pragma unroll
            for (int i = 0; i < 4; i++)
#pragma unroll
                for (int j = 0; j < 4; j++) {
                    accp[i][j] += a[i] * bb[j];
                    accm[i][j] += a[i] * bs[j];
                }
        }
    }

#pragma unroll
    for (int i = 0; i < 4; i++) {
        const int t = t0 + ty * 4 + i;
        const float st = (t & 1) ? -1.f : 1.f;
        const size_t row = (size_t)(b * S_ + t) * UCOLS;
#pragma unroll
        for (int j = 0; j < 4; j++) {
            const int d = d0 + tx * 4 + j;
            U[row + k * D_ + d]          = accp[i][j];
            U[row + (K_ + k) * D_ + d]   = st * accm[i][j];
        }
    }
}

// ---------------- rmsnorm + AR column scatter ----------------
// h[row] = x[row] * rsqrt(mean(x^2)+eps) * w ; also writes h into U's AR slots:
// U[row+j][SPECC + j*D + d] = h[row][d]  (same batch), and zeroes missing-history slots.
__global__ __launch_bounds__(256) void rmsnorm_k(
    const float* __restrict__ x, const float* __restrict__ w,
    float* __restrict__ h, float* __restrict__ U)
{
    __shared__ float red[256];
    const int row = blockIdx.x;
    const int t = row & (S_ - 1);
    const int tid = threadIdx.x;

    const float v0 = x[(size_t)row * D_ + tid];
    const float v1 = x[(size_t)row * D_ + 256 + tid];
    red[tid] = v0 * v0 + v1 * v1;
    __syncthreads();
    for (int s = 128; s > 0; s >>= 1) {
        if (tid < s) red[tid] += red[tid + s];
        __syncthreads();
    }
    const float scale = rsqrtf(red[0] * (1.f / D_) + EPS_);
    const float h0 = v0 * scale * w[tid];
    const float h1 = v1 * scale * w[tid + 256];
    h[(size_t)row * D_ + tid] = h0;
    h[(size_t)row * D_ + 256 + tid] = h1;

#pragma unroll
    for (int j = 0; j < KU_; j++) {
        if (t + j < S_) {  // write h[t] into row t+j's AR slot j
            const size_t base = (size_t)(row + j) * UCOLS + SPECC + j * D_;
            U[base + tid] = h0;
            U[base + 256 + tid] = h1;
        }
        if (t < j) {       // this row has no history for slot j -> zero
            const size_t base = (size_t)row * UCOLS + SPECC + j * D_;
            U[base + tid] = 0.f;
            U[base + 256 + tid] = 0.f;
        }
    }
}

// ---------------- fused weight fill: W[o][col], (N=512, K=17920) NT layout ----------------
__global__ __launch_bounds__(256) void wfill_k(
    const float* __restrict__ sigma, const float* __restrict__ mp,
    const float* __restrict__ mm, const float* __restrict__ mu,
    float* __restrict__ W)
{
    const size_t idx = (size_t)blockIdx.x * 256 + threadIdx.x;
    if (idx >= (size_t)D_ * UCOLS) return;
    const int o = (int)(idx / UCOLS);
    const int col = (int)(idx % UCOLS);
    float v;
    if (col < K_ * D_) {
        const int k = col / D_, d = col % D_;
        v = sqrtf(sqrtf(sigma[k])) * mp[((size_t)k * D_ + d) * D_ + o];
    } else if (col < SPECC) {
        const int c = col - K_ * D_;
        const int k = c / D_, d = c % D_;
        v = sqrtf(sqrtf(sigma[k])) * mm[((size_t)k * D_ + d) * D_ + o];
    } else {
        const int c = col - SPECC;
        const int j = c / D_, d = c % D_;
        v = mu[((size_t)j * D_ + d) * D_ + o];
    }
    W[idx] = v;
}

// ---------------- elementwise kernels ----------------
__global__ __launch_bounds__(256) void silu_k(const float* __restrict__ m1, float* __restrict__ m2)
{
    const int idx = blockIdx.x * 256 + threadIdx.x;   // over R_*H_
    const int r = idx >> 11;           // / H_
    const int j = idx & (H_ - 1);
    const float y = m1[(size_t)r * (2 * H_) + j];
    const float g = m1[(size_t)r * (2 * H_) + H_ + j];
    m2[idx] = y * g / (1.f + expf(-g));
}

__global__ __launch_bounds__(256) void copy_k(float* __restrict__ dst, const float* __restrict__ src)
{
    const int i = blockIdx.x * 256 + threadIdx.x;     // over R_*D_/4
    ((float4*)dst)[i] = ((const float4*)src)[i];
}

__global__ __launch_bounds__(256) void add_k(float* __restrict__ dst, const float* __restrict__ src)
{
    const int i = blockIdx.x * 256 + threadIdx.x;     // over R_*D_/4
    float4 a = ((const float4*)dst)[i];
    float4 b = ((const float4*)src)[i];
    a.x += b.x; a.y += b.y; a.z += b.z; a.w += b.w;
    ((float4*)dst)[i] = a;
}

// ---------------- launch ----------------
extern "C" void kernel_launch(void* const* d_in, const int* in_sizes, int n_in,
                              void* d_out, int out_size)
{
    const float* inputs  = (const float*)d_in[0];
    const float* sigma   = (const float*)d_in[1];
    const float* phi     = (const float*)d_in[2];
    const float* in_proj = (const float*)d_in[3];
    const float* rn_w    = (const float*)d_in[4];
    const float* M_u     = (const float*)d_in[5];
    const float* M_p     = (const float*)d_in[6];
    const float* M_m     = (const float*)d_in[7];
    const float* fc1     = (const float*)d_in[8];
    const float* fc2     = (const float*)d_in[9];
    const float* out_w   = (const float*)d_in[10];
    float* out = (float*)d_out;

    float *x, *z, *h, *U, *W, *m1, *m2;
    cudaGetSymbolAddress((void**)&x,  g_x);
    cudaGetSymbolAddress((void**)&z,  g_z);
    cudaGetSymbolAddress((void**)&h,  g_h);
    cudaGetSymbolAddress((void**)&U,  g_U);
    cudaGetSymbolAddress((void**)&W,  g_W);
    cudaGetSymbolAddress((void**)&m1, g_m1);
    cudaGetSymbolAddress((void**)&m2, g_m2);

    const int ew_blocks = (R_ * D_ / 4) / 256;                 // 1024
    const int wfill_blocks = (int)(((size_t)D_ * UCOLS + 255) / 256);
    const int silu_blocks = (R_ * H_) / 256;                   // 16384

    for (int m = 0; m < M_; m++) {
        // x = inputs @ in_proj[m]^T   (2048 x 512, K=64)
        gemm_nt<<<dim3(D_ / 64, R_ / 64), 256>>>(
            inputs, in_proj + (size_t)m * D_ * DIN_, x, R_, D_, DIN_, 0);

        for (int l = 0; l < L_; l++) {
            const int ml = m * L_ + l;

            copy_k<<<ew_blocks, 256>>>(z, x);                       // z = x
            rmsnorm_k<<<R_, 256>>>(x, rn_w + (size_t)ml * D_, h, U); // h + AR cols of U
            conv_k<<<dim3(D_ / 64, S_ / 64, B_ * K_), 256>>>(h, phi, U);
            wfill_k<<<wfill_blocks, 256>>>(
                sigma,
                M_p + (size_t)ml * K_ * D_ * D_,
                M_m + (size_t)ml * K_ * D_ * D_,
                M_u + (size_t)ml * KU_ * D_ * D_,
                W);
            // x += U @ W^T  (spec + AR), K=17920
            gemm_nt<<<dim3(D_ / 64, R_ / 64), 256>>>(U, W, x, R_, D_, UCOLS, 1);

            // MLP
            gemm_nt<<<dim3(2 * H_ / 64, R_ / 64), 256>>>(
                x, fc1 + (size_t)ml * 2 * H_ * D_, m1, R_, 2 * H_, D_, 0);
            silu_k<<<silu_blocks, 256>>>(m1, m2);
            gemm_nt<<<dim3(D_ / 64, R_ / 64), 256>>>(
                m2, fc2 + (size_t)ml * D_ * H_, x, R_, D_, H_, 1);

            add_k<<<ew_blocks, 256>>>(x, z);                        // x += z
        }

        // preds += x @ out_proj[m]^T  (N=64); m=0 overwrites poison, m=1 accumulates
        gemm_nt<<<dim3(DIN_ / 64, R_ / 64), 256>>>(
            x, out_w + (size_t)m * DIN_ * D_, out, R_, DIN_, D_, m);
    }
    (void)in_sizes; (void)n_in; (void)out_size;
}

// round 3
// speedup vs baseline: 2.4884x; 2.4884x over previous
#include <cuda_runtime.h>
#include <cstddef>

// ---------------- problem constants ----------------
#define B_    2
#define S_    1024
#define DIN_  64
#define D_    512
#define K_    16
#define KU_   3
#define L_    2
#define M_    2
#define H_    2048
#define R_    (B_ * S_)                 // 2048 rows (b*S + t)
#define SPECC (2 * K_ * D_)             // 16384 spectral columns of U
#define UCOLS (SPECC + KU_ * D_)        // 17920 = spectral + AR columns
#define EPS_  1e-5f

// ---------------- scratch (static device globals; no allocation) ----------------
__device__ float g_x[R_ * D_];
__device__ float g_z[R_ * D_];
__device__ float g_h[R_ * D_];
__device__ float g_U[(size_t)R_ * UCOLS];            // [Up | Um | h, h<<1, h<<2]
__device__ float g_W[(size_t)D_ * UCOLS];            // fused [sig4*mp | sig4*mm | M_u]
__device__ float g_m1[(size_t)R_ * 2 * H_];
__device__ float g_m2[(size_t)R_ * H_];

// ---------------- tf32 helpers ----------------
__device__ __forceinline__ unsigned f2tf(float f) {
    unsigned u;
    asm("cvt.rna.tf32.f32 %0, %1;" : "=r"(u) : "f"(f));
    return u;
}

__device__ __forceinline__ void mma_tf32(float c[4],
                                         unsigned a0, unsigned a1, unsigned a2, unsigned a3,
                                         unsigned b0, unsigned b1) {
    asm volatile(
        "mma.sync.aligned.m16n8k8.row.col.f32.tf32.tf32.f32 "
        "{%0,%1,%2,%3},{%4,%5,%6,%7},{%8,%9},{%0,%1,%2,%3};\n"
        : "+f"(c[0]), "+f"(c[1]), "+f"(c[2]), "+f"(c[3])
        : "r"(a0), "r"(a1), "r"(a2), "r"(a3), "r"(b0), "r"(b1));
}

// ---------------- tf32 NT GEMM: C(M,N) = A(M,K) * B(N,K)^T ----------------
// 256 threads = 8 warps, warp grid (BM/WM) x (BN/WN) == 8, BK=32.
// M % BM == 0, N % BN == 0, K % 32 == 0.
template<int BM, int BN, int WM, int WN>
__global__ __launch_bounds__(256) void gemm_nt_tc(
    const float* __restrict__ A, const float* __restrict__ B, float* __restrict__ C,
    int M, int N, int K, int accum)
{
    constexpr int WARPS_M = BM / WM;
    constexpr int MT = WM / 16;
    constexpr int NT = WN / 8;
    __shared__ unsigned As[BM][36];
    __shared__ unsigned Bs[BN][36];

    const int bm = blockIdx.y * BM;
    const int bn = blockIdx.x * BN;
    const int tid  = threadIdx.x;
    const int lane = tid & 31;
    const int warp = tid >> 5;
    const int wm = (warp % WARPS_M) * WM;
    const int wn = (warp / WARPS_M) * WN;
    const int g  = lane >> 2;
    const int tg = lane & 3;

    const int lr = tid >> 3;         // 0..31
    const int lk = (tid & 7) * 4;    // 0..28

    float acc[MT][NT][4] = {};

    for (int k0 = 0; k0 < K; k0 += 32) {
        float4 va[BM / 32], vb[BN / 32];
#pragma unroll
        for (int r = 0; r < BM / 32; r++)
            va[r] = *(const float4*)&A[(size_t)(bm + lr + 32 * r) * K + k0 + lk];
#pragma unroll
        for (int r = 0; r < BN / 32; r++)
            vb[r] = *(const float4*)&B[(size_t)(bn + lr + 32 * r) * K + k0 + lk];
        __syncthreads();
#pragma unroll
        for (int r = 0; r < BM / 32; r++) {
            As[lr + 32 * r][lk + 0] = f2tf(va[r].x);
            As[lr + 32 * r][lk + 1] = f2tf(va[r].y);
            As[lr + 32 * r][lk + 2] = f2tf(va[r].z);
            As[lr + 32 * r][lk + 3] = f2tf(va[r].w);
        }
#pragma unroll
        for (int r = 0; r < BN / 32; r++) {
            Bs[lr + 32 * r][lk + 0] = f2tf(vb[r].x);
            Bs[lr + 32 * r][lk + 1] = f2tf(vb[r].y);
            Bs[lr + 32 * r][lk + 2] = f2tf(vb[r].z);
            Bs[lr + 32 * r][lk + 3] = f2tf(vb[r].w);
        }
        __syncthreads();

#pragma unroll
        for (int ks = 0; ks < 4; ks++) {
            const int kb = ks * 8;
            unsigned af[MT][4], bf[NT][2];
#pragma unroll
            for (int mt = 0; mt < MT; mt++) {
                const int row = wm + mt * 16;
                af[mt][0] = As[row + g    ][kb + tg    ];
                af[mt][1] = As[row + g + 8][kb + tg    ];
                af[mt][2] = As[row + g    ][kb + tg + 4];
                af[mt][3] = As[row + g + 8][kb + tg + 4];
            }
#pragma unroll
            for (int nt = 0; nt < NT; nt++) {
                const int col = wn + nt * 8;
                bf[nt][0] = Bs[col + g][kb + tg    ];
                bf[nt][1] = Bs[col + g][kb + tg + 4];
            }
#pragma unroll
            for (int mt = 0; mt < MT; mt++)
#pragma unroll
                for (int nt = 0; nt < NT; nt++)
                    mma_tf32(acc[mt][nt], af[mt][0], af[mt][1], af[mt][2], af[mt][3],
                             bf[nt][0], bf[nt][1]);
        }
        __syncthreads();
    }

#pragma unroll
    for (int mt = 0; mt < MT; mt++) {
        const int r0 = bm + wm + mt * 16 + g;
        const int r1 = r0 + 8;
#pragma unroll
        for (int nt = 0; nt < NT; nt++) {
            const int col = bn + wn + nt * 8 + 2 * tg;
            float2* p0 = (float2*)&C[(size_t)r0 * N + col];
            float2* p1 = (float2*)&C[(size_t)r1 * N + col];
            float2 v0 = make_float2(acc[mt][nt][0], acc[mt][nt][1]);
            float2 v1 = make_float2(acc[mt][nt][2], acc[mt][nt][3]);
            if (accum) {
                float2 o0 = *p0, o1 = *p1;
                v0.x += o0.x; v0.y += o0.y; v1.x += o1.x; v1.y += o1.y;
            }
            *p0 = v0;
            *p1 = v1;
        }
    }
}

// ---------------- causal spectral conv via Toeplitz tf32 MMA ----------------
// grid: (D/64, S/128, B*K). Up[t,d]=sum_i phi[t-i]h[i,d]; Um[t,d]=st*sum_i phi[t-i]*si*h[i,d].
__global__ __launch_bounds__(256) void conv_tc(
    const float* __restrict__ h, const float* __restrict__ phi, float* __restrict__ U)
{
    __shared__ unsigned Xs[32][68];   // [i][d]
    __shared__ unsigned Ps[160];      // phi lags (tf32 bits), zero-filled OOB

    const int d0 = blockIdx.x * 64;
    const int t0 = blockIdx.y * 128;
    const int b  = blockIdx.z >> 4;
    const int k  = blockIdx.z & 15;
    const int tid  = threadIdx.x;
    const int lane = tid & 31;
    const int warp = tid >> 5;
    const int wm = (warp & 3) * 32;   // t offset within block
    const int wn = (warp >> 2) * 32;  // d offset within block
    const int g  = lane >> 2;
    const int tg = lane & 3;
    const unsigned sx = (tg & 1) ? 0x80000000u : 0u;  // sign of i-index (parity of tg; i0,kb even)

    float accp[2][4][4] = {};
    float accm[2][4][4] = {};

    const int xr = tid >> 4;          // 0..15
    const int xc = (tid & 15) * 4;    // 0..60
    const int imax = t0 + 128;        // causal bound (<= S_ always)

    for (int i0 = 0; i0 < imax; i0 += 32) {
        float4 v0 = *(const float4*)&h[(size_t)(b * S_ + i0 + xr     ) * D_ + d0 + xc];
        float4 v1 = *(const float4*)&h[(size_t)(b * S_ + i0 + xr + 16) * D_ + d0 + xc];
        float pv = 0.f;
        if (tid < 159) {
            const int lag = t0 - i0 - 31 + tid;
            if (lag >= 0 && lag < S_) pv = phi[lag * K_ + k];
        }
        __syncthreads();
        Xs[xr][xc + 0] = f2tf(v0.x); Xs[xr][xc + 1] = f2tf(v0.y);
        Xs[xr][xc + 2] = f2tf(v0.z); Xs[xr][xc + 3] = f2tf(v0.w);
        Xs[xr + 16][xc + 0] = f2tf(v1.x); Xs[xr + 16][xc + 1] = f2tf(v1.y);
        Xs[xr + 16][xc + 2] = f2tf(v1.z); Xs[xr + 16][xc + 3] = f2tf(v1.w);
        if (tid < 159) Ps[tid] = f2tf(pv);
        if (tid == 159) Ps[159] = 0u;
        __syncthreads();

#pragma unroll
        for (int ks = 0; ks < 4; ks++) {
            const int kb = ks * 8;
            unsigned af[2][4], bf[4][2];
#pragma unroll
            for (int mt = 0; mt < 2; mt++) {
                const int row = wm + mt * 16;
                // A[m][kk] = phi[(t0+m) - (i0+kb+kk)] = Ps[m - kb - kk + 31]
                af[mt][0] = Ps[row + g     - kb - tg     + 31];
                af[mt][1] = Ps[row + g + 8 - kb - tg     + 31];
                af[mt][2] = Ps[row + g     - kb - tg - 4 + 31];
                af[mt][3] = Ps[row + g + 8 - kb - tg - 4 + 31];
            }
#pragma unroll
            for (int nt = 0; nt < 4; nt++) {
                const int col = wn + nt * 8 + g;
                bf[nt][0] = Xs[kb + tg    ][col];
                bf[nt][1] = Xs[kb + tg + 4][col];
            }
#pragma unroll
            for (int mt = 0; mt < 2; mt++)
#pragma unroll
                for (int nt = 0; nt < 4; nt++) {
                    mma_tf32(accp[mt][nt], af[mt][0], af[mt][1], af[mt][2], af[mt][3],
                             bf[nt][0], bf[nt][1]);
                    mma_tf32(accm[mt][nt],
                             af[mt][0] ^ sx, af[mt][1] ^ sx, af[mt][2] ^ sx, af[mt][3] ^ sx,
                             bf[nt][0], bf[nt][1]);
                }
        }
        __syncthreads();
    }

#pragma unroll
    for (int mt = 0; mt < 2; mt++) {
        const int t0r = t0 + wm + mt * 16 + g;
#pragma unroll
        for (int half = 0; half < 2; half++) {
            const int t = t0r + half * 8;
            const float st = (t & 1) ? -1.f : 1.f;
            const size_t row = (size_t)(b * S_ + t) * UCOLS;
#pragma unroll
            for (int nt = 0; nt < 4; nt++) {
                const int d = d0 + wn + nt * 8 + 2 * tg;
                const float cp0 = accp[mt][nt][half * 2 + 0];
                const float cp1 = accp[mt][nt][half * 2 + 1];
                const float cm0 = accm[mt][nt][half * 2 + 0];
                const float cm1 = accm[mt][nt][half * 2 + 1];
                *(float2*)&U[row + (size_t)k * D_ + d]        = make_float2(cp0, cp1);
                *(float2*)&U[row + (size_t)(K_ + k) * D_ + d] = make_float2(st * cm0, st * cm1);
            }
        }
    }
}

// ---------------- fp32 NT GEMM (kept for tiny out_proj: N=64) ----------------
__global__ __launch_bounds__(256) void gemm_nt(
    const float* __restrict__ A, const float* __restrict__ B, float* __restrict__ C,
    int M, int N, int K, int accum)
{
    __shared__ float As[16][65];
    __shared__ float Bs[16][65];
    const int bm = blockIdx.y * 64;
    const int bn = blockIdx.x * 64;
    const int tid = threadIdx.x;
    const int tx = tid & 15;
    const int ty = tid >> 4;
    const int lr = tid >> 2;
    const int lk = (tid & 3) << 2;

    const float* Ap = A + (size_t)(bm + lr) * K + lk;
    const float* Bp = B + (size_t)(bn + lr) * K + lk;

    float acc[4][4] = {};

    for (int k0 = 0; k0 < K; k0 += 16) {
        float4 av = *(const float4*)(Ap + k0);
        float4 bv = *(const float4*)(Bp + k0);
        __syncthreads();
        As[lk + 0][lr] = av.x; As[lk + 1][lr] = av.y;
        As[lk + 2][lr] = av.z; As[lk + 3][lr] = av.w;
        Bs[lk + 0][lr] = bv.x; Bs[lk + 1][lr] = bv.y;
        Bs[lk + 2][lr] = bv.z; Bs[lk + 3][lr] = bv.w;
        __syncthreads();
#pragma unroll
        for (int kk = 0; kk < 16; kk++) {
            float a[4], b[4];
#pragma unroll
            for (int i = 0; i < 4; i++) a[i] = As[kk][ty * 4 + i];
#pragma unroll
            for (int j = 0; j < 4; j++) b[j] = Bs[kk][tx * 4 + j];
#pragma unroll
            for (int i = 0; i < 4; i++)
#pragma unroll
                for (int j = 0; j < 4; j++)
                    acc[i][j] += a[i] * b[j];
        }
    }

#pragma unroll
    for (int i = 0; i < 4; i++) {
        const int r = bm + ty * 4 + i;
#pragma unroll
        for (int j = 0; j < 4; j++) {
            const int c = bn + tx * 4 + j;
            const size_t idx = (size_t)r * N + c;
            C[idx] = accum ? (C[idx] + acc[i][j]) : acc[i][j];
        }
    }
}

// ---------------- rmsnorm + AR column scatter ----------------
__global__ __launch_bounds__(256) void rmsnorm_k(
    const float* __restrict__ x, const float* __restrict__ w,
    float* __restrict__ h, float* __restrict__ U)
{
    __shared__ float red[256];
    const int row = blockIdx.x;
    const int t = row & (S_ - 1);
    const int tid = threadIdx.x;

    const float v0 = x[(size_t)row * D_ + tid];
    const float v1 = x[(size_t)row * D_ + 256 + tid];
    red[tid] = v0 * v0 + v1 * v1;
    __syncthreads();
    for (int s = 128; s > 0; s >>= 1) {
        if (tid < s) red[tid] += red[tid + s];
        __syncthreads();
    }
    const float scale = rsqrtf(red[0] * (1.f / D_) + EPS_);
    const float h0 = v0 * scale * w[tid];
    const float h1 = v1 * scale * w[tid + 256];
    h[(size_t)row * D_ + tid] = h0;
    h[(size_t)row * D_ + 256 + tid] = h1;

#pragma unroll
    for (int j = 0; j < KU_; j++) {
        if (t + j < S_) {
            const size_t base = (size_t)(row + j) * UCOLS + SPECC + j * D_;
            U[base + tid] = h0;
            U[base + 256 + tid] = h1;
        }
        if (t < j) {
            const size_t base = (size_t)row * UCOLS + SPECC + j * D_;
            U[base + tid] = 0.f;
            U[base + 256 + tid] = 0.f;
        }
    }
}

// ---------------- fused weight fill ----------------
__global__ __launch_bounds__(256) void wfill_k(
    const float* __restrict__ sigma, const float* __restrict__ mp,
    const float* __restrict__ mm, const float* __restrict__ mu,
    float* __restrict__ W)
{
    const size_t idx = (size_t)blockIdx.x * 256 + threadIdx.x;
    if (idx >= (size_t)D_ * UCOLS) return;
    const int o = (int)(idx / UCOLS);
    const int col = (int)(idx % UCOLS);
    float v;
    if (col < K_ * D_) {
        const int k = col / D_, d = col % D_;
        v = sqrtf(sqrtf(sigma[k])) * mp[((size_t)k * D_ + d) * D_ + o];
    } else if (col < SPECC) {
        const int c = col - K_ * D_;
        const int k = c / D_, d = c % D_;
        v = sqrtf(sqrtf(sigma[k])) * mm[((size_t)k * D_ + d) * D_ + o];
    } else {
        const int c = col - SPECC;
        const int j = c / D_, d = c % D_;
        v = mu[((size_t)j * D_ + d) * D_ + o];
    }
    W[idx] = v;
}

// ---------------- elementwise kernels ----------------
__global__ __launch_bounds__(256) void silu_k(const float* __restrict__ m1, float* __restrict__ m2)
{
    const int idx = blockIdx.x * 256 + threadIdx.x;
    const int r = idx >> 11;
    const int j = idx & (H_ - 1);
    const float y = m1[(size_t)r * (2 * H_) + j];
    const float g = m1[(size_t)r * (2 * H_) + H_ + j];
    m2[idx] = y * g / (1.f + expf(-g));
}

__global__ __launch_bounds__(256) void copy_k(float* __restrict__ dst, const float* __restrict__ src)
{
    const int i = blockIdx.x * 256 + threadIdx.x;
    ((float4*)dst)[i] = ((const float4*)src)[i];
}

__global__ __launch_bounds__(256) void add_k(float* __restrict__ dst, const float* __restrict__ src)
{
    const int i = blockIdx.x * 256 + threadIdx.x;
    float4 a = ((const float4*)dst)[i];
    float4 b = ((const float4*)src)[i];
    a.x += b.x; a.y += b.y; a.z += b.z; a.w += b.w;
    ((float4*)dst)[i] = a;
}

// ---------------- launch ----------------
extern "C" void kernel_launch(void* const* d_in, const int* in_sizes, int n_in,
                              void* d_out, int out_size)
{
    const float* inputs  = (const float*)d_in[0];
    const float* sigma   = (const float*)d_in[1];
    const float* phi     = (const float*)d_in[2];
    const float* in_proj = (const float*)d_in[3];
    const float* rn_w    = (const float*)d_in[4];
    const float* M_u     = (const float*)d_in[5];
    const float* M_p     = (const float*)d_in[6];
    const float* M_m     = (const float*)d_in[7];
    const float* fc1     = (const float*)d_in[8];
    const float* fc2     = (const float*)d_in[9];
    const float* out_w   = (const float*)d_in[10];
    float* out = (float*)d_out;

    float *x, *z, *h, *U, *W, *m1, *m2;
    cudaGetSymbolAddress((void**)&x,  g_x);
    cudaGetSymbolAddress((void**)&z,  g_z);
    cudaGetSymbolAddress((void**)&h,  g_h);
    cudaGetSymbolAddress((void**)&U,  g_U);
    cudaGetSymbolAddress((void**)&W,  g_W);
    cudaGetSymbolAddress((void**)&m1, g_m1);
    cudaGetSymbolAddress((void**)&m2, g_m2);

    const int ew_blocks = (R_ * D_ / 4) / 256;
    const int wfill_blocks = (int)(((size_t)D_ * UCOLS + 255) / 256);
    const int silu_blocks = (R_ * H_) / 256;

    for (int m = 0; m < M_; m++) {
        // x = inputs @ in_proj[m]^T   (2048 x 512, K=64)
        gemm_nt_tc<64, 64, 16, 32><<<dim3(D_ / 64, R_ / 64), 256>>>(
            inputs, in_proj + (size_t)m * D_ * DIN_, x, R_, D_, DIN_, 0);

        for (int l = 0; l < L_; l++) {
            const int ml = m * L_ + l;

            copy_k<<<ew_blocks, 256>>>(z, x);
            rmsnorm_k<<<R_, 256>>>(x, rn_w + (size_t)ml * D_, h, U);
            conv_tc<<<dim3(D_ / 64, S_ / 128, B_ * K_), 256>>>(h, phi, U);
            wfill_k<<<wfill_blocks, 256>>>(
                sigma,
                M_p + (size_t)ml * K_ * D_ * D_,
                M_m + (size_t)ml * K_ * D_ * D_,
                M_u + (size_t)ml * KU_ * D_ * D_,
                W);
            // x += U @ W^T  (spec + AR), K=17920
            gemm_nt_tc<64, 64, 16, 32><<<dim3(D_ / 64, R_ / 64), 256>>>(
                U, W, x, R_, D_, UCOLS, 1);

            // MLP
            gemm_nt_tc<128, 128, 32, 64><<<dim3(2 * H_ / 128, R_ / 128), 256>>>(
                x, fc1 + (size_t)ml * 2 * H_ * D_, m1, R_, 2 * H_, D_, 0);
            silu_k<<<silu_blocks, 256>>>(m1, m2);
            gemm_nt_tc<64, 64, 16, 32><<<dim3(D_ / 64, R_ / 64), 256>>>(
                m2, fc2 + (size_t)ml * D_ * H_, x, R_, D_, H_, 1);

            add_k<<<ew_blocks, 256>>>(x, z);
        }

        // preds += x @ out_proj[m]^T  (N=64)
        gemm_nt<<<dim3(DIN_ / 64, R_ / 64), 256>>>(
            x, out_w + (size_t)m * DIN_ * D_, out, R_, DIN_, D_, m);
    }
    (void)in_sizes; (void)n_in; (void)out_size;
}